// round 8
// baseline (speedup 1.0000x reference)
#include <cuda_runtime.h>
#include <cstdint>

typedef unsigned long long ull;

// Problem constants
#define NB   16
#define NT   8
#define NK   64
#define CIN  128
#define COUT 128
#define HH   64
#define WW   64

// g_lp: fp16x2 weights in m16n8k16 A-fragment order:
// [b][ij 25][kc 8][mt 8][lane 32][q 4]   (b stride 204800, ij stride 8192, kc stride 1024)
// element (oc, cin): kc=cin>>4, cp=(cin>>1)&7, lo=cin&1 (lo->low half of fp16x2);
//                    kb=cp&3, qk=cp>>2; rl=oc&15, mt=oc>>4, rg=rl&7, qr=rl>>3;
//                    lane=rg*4+kb, q=qk*2+qr
__device__ uint32_t g_lp[NB * 204800];

// ---------------- helpers ----------------
__device__ __forceinline__ ull bcast2(float x) {
    ull r; asm("mov.b64 %0, {%1, %1};" : "=l"(r) : "f"(x)); return r;
}
__device__ __forceinline__ ull pack2(float lo, float hi) {
    ull r; asm("mov.b64 %0, {%1, %2};" : "=l"(r) : "f"(lo), "f"(hi)); return r;
}
__device__ __forceinline__ void unpack2(ull v, float& lo, float& hi) {
    asm("mov.b64 {%0, %1}, %2;" : "=f"(lo), "=f"(hi) : "l"(v));
}
__device__ __forceinline__ void ffma2(ull& d, ull a, ull b) {
    asm("fma.rn.f32x2 %0, %1, %2, %3;" : "=l"(d) : "l"(a), "l"(b), "l"(d));
}
// pack two f32 into fp16x2: lo -> low 16 bits, hi -> high 16 bits
__device__ __forceinline__ uint32_t pack_h2(float lo, float hi) {
    uint32_t v; asm("cvt.rn.f16x2.f32 %0, %1, %2;" : "=r"(v) : "f"(hi), "f"(lo)); return v;
}
// m16n8k16 fp16 MMA: D(16x8,f32) += A(16x16 f16, row) * B(16x8 f16, col)
__device__ __forceinline__ void mma_f16(float* d, const uint4& a, uint32_t b0, uint32_t b1) {
    asm volatile(
        "mma.sync.aligned.m16n8k16.row.col.f32.f16.f16.f32 "
        "{%0,%1,%2,%3}, {%4,%5,%6,%7}, {%8,%9}, {%0,%1,%2,%3};\n"
        : "+f"(d[0]), "+f"(d[1]), "+f"(d[2]), "+f"(d[3])
        : "r"(a.x), "r"(a.y), "r"(a.z), "r"(a.w), "r"(b0), "r"(b1));
}

// ---------------- lp kernel: coeff (inline) + fragment-ordered fp16x2 params for 8 b ----------------
// Covers b = b_base .. b_base+7. One thread per (o, cin-pair cp, ij).
__global__ void lp_kernel(const float* __restrict__ W, const float* __restrict__ tf, int b_base) {
    __shared__ ull sc[NK * 4];    // [k][pair p of 4], pair p -> b = b_base + 2p (+1)
    int tid = threadIdx.x;        // 256

    // inline coeff: 256 entries, 1 per thread
    {
        int k = tid >> 2;
        int p = tid & 3;
        int b0 = b_base + 2 * p, b1 = b0 + 1;
        float s0 = 0.f, s1 = 0.f;
#pragma unroll
        for (int tt = 0; tt < NT; tt++) {
            s0 += tf[(b0 * NT + tt) * NK + k];
            s1 += tf[(b1 * NT + tt) * NK + k];
        }
        sc[k * 4 + p] = pack2(s0 * 0.125f, s1 * 0.125f);
    }
    __syncthreads();

    int idx = blockIdx.x * 256 + tid;   // < 204800 (grid 800)
    int o   = idx / 1600;
    int rem = idx - o * 1600;
    int cp  = rem / 25;
    int ij  = rem - cp * 25;

    const float* W0 = W + o * 3200 + (2 * cp) * 25 + ij;        // even cin
    const float* W1 = W0 + 25;                                  // odd cin

    ull a0[4], a1[4];
#pragma unroll
    for (int p = 0; p < 4; p++) { a0[p] = 0ULL; a1[p] = 0ULL; }

#pragma unroll 4
    for (int k = 0; k < NK; k++) {
        ull w0 = bcast2(W0[k * 409600]);
        ull w1 = bcast2(W1[k * 409600]);
#pragma unroll
        for (int p = 0; p < 4; p++) {
            ffma2(a0[p], w0, sc[k * 4 + p]);
            ffma2(a1[p], w1, sc[k * 4 + p]);
        }
    }

    // fragment-order output index
    int kc = cp >> 3, cpl = cp & 7;
    int kb = cpl & 3, qk = cpl >> 2;
    int rl = o & 15, mt = o >> 4;
    int rg = rl & 7, qr = rl >> 3;
    int outoff = ij * 8192 + kc * 1024 + mt * 128 + (rg * 4 + kb) * 4 + (qk * 2 + qr);

#pragma unroll
    for (int p = 0; p < 4; p++) {
        float e0, e1, d0, d1;
        unpack2(a0[p], e0, e1);   // even cin, b = b_base+2p / +2p+1
        unpack2(a1[p], d0, d1);   // odd  cin
        g_lp[(b_base + 2 * p) * 204800 + outoff]     = pack_h2(e0, d0);
        g_lp[(b_base + 2 * p + 1) * 204800 + outoff] = pack_h2(e1, d1);
    }
}

// ---------------- conv kernel: implicit-GEMM via mma.sync fp16 k16 ----------------
// CTA: (b_base + by) x one 4-row tile. 512 threads, 16 warps.
// Warp (mrow = wid&3, ro = wid>>2): 32 oc x 64 w of output row r0+ro.
// x tile in smem: 8 cin-pairs x 8 rows x 72 w fp16x2 (stride 584 -> conflict-free B frags).
#define XSTRIDE 584

__global__ void __launch_bounds__(512, 1)
conv_kernel(const float* __restrict__ x, float* __restrict__ out, int b_base) {
    __shared__ uint32_t sx[8 * XSTRIDE];   // 18688 B

    int tid  = threadIdx.x;
    int lane = tid & 31, wid = tid >> 5;
    int mrow = wid & 3, ro = wid >> 2;
    int b    = b_base + blockIdx.y;

    const float*    xb  = x + b * CIN * (HH * WW);
    const uint32_t* lpb = g_lp + b * 204800;
    const uint32_t* abase = lpb + mrow * 256 + lane * 4;   // mt = 2*mrow

    int g  = lane >> 2;
    int m4 = lane & 3;

    int r0 = blockIdx.x * 4;

    float d[2][8][4];
#pragma unroll
    for (int mt = 0; mt < 2; mt++)
#pragma unroll
        for (int nt = 0; nt < 8; nt++)
#pragma unroll
            for (int q = 0; q < 4; q++) d[mt][nt][q] = 0.f;

    // prefetch A fragments for it = 0 (ij=0, kc=0); mt stride = 128 words = 32 uint4
    uint4 An0, An1;
    {
        const uint4* p = (const uint4*)abase;
        An0 = p[0]; An1 = p[32];
    }

    for (int it = 0; it < 200; it++) {
        int c0i = it / 25, ij = it - c0i * 25;

        if (ij == 0) {
            __syncthreads();
            int c0 = c0i * 16;
            for (int q = tid; q < 8 * 576; q += 512) {
                int pr = q / 576, r = q - pr * 576;
                int ur = r / 72, uc = r - ur * 72;
                int gh = r0 + ur - 2, gw = uc - 2;
                float v0 = 0.f, v1 = 0.f;
                if (gh >= 0 && gh < HH && gw >= 0 && gw < WW) {
                    const float* px = xb + ((c0 + 2 * pr) << 12) + (gh << 6) + gw;
                    v0 = px[0];
                    v1 = px[1 << 12];
                }
                sx[pr * XSTRIDE + ur * 72 + uc] = pack_h2(v0, v1);
            }
            __syncthreads();
        }

        uint4 A0 = An0, A1 = An1;
        if (it + 1 < 200) {
            int itn = it + 1;
            int c0n = itn / 25, ijn = itn - c0n * 25;
            const uint4* p = (const uint4*)(abase + ijn * 8192 + c0n * 1024);
            An0 = p[0]; An1 = p[32];
        }

        int i = ij / 5, j = ij - i * 5;
        int boff = m4 * XSTRIDE + (ro + i) * 72 + j + g;
#pragma unroll
        for (int nt = 0; nt < 8; nt++) {
            uint32_t b0 = sx[boff + nt * 8];
            uint32_t b1 = sx[boff + nt * 8 + 4 * XSTRIDE];
            mma_f16(d[0][nt], A0, b0, b1);
            mma_f16(d[1][nt], A1, b0, b1);
        }
    }

    // epilogue: D(row=g/g+8, col=2*m4/2*m4+1) per (mt, nt)
    int h = r0 + ro;
#pragma unroll
    for (int mt = 0; mt < 2; mt++) {
#pragma unroll
        for (int qr = 0; qr < 2; qr++) {
            int oc = mrow * 32 + mt * 16 + g + qr * 8;
            float* op = out + ((b * COUT + oc) * HH + h) * WW;
#pragma unroll
            for (int nt = 0; nt < 8; nt++) {
                float2 v;
                v.x = d[mt][nt][qr * 2];
                v.y = d[mt][nt][qr * 2 + 1];
                *(float2*)(op + nt * 8 + 2 * m4) = v;
            }
        }
    }
}

// ---------------- launch: fork-join overlap of lpB with convA ----------------
static cudaStream_t make_stream() {
    cudaStream_t s;
    cudaStreamCreateWithFlags(&s, cudaStreamNonBlocking);
    return s;
}
static cudaEvent_t make_event() {
    cudaEvent_t e;
    cudaEventCreateWithFlags(&e, cudaEventDisableTiming);
    return e;
}

extern "C" void kernel_launch(void* const* d_in, const int* in_sizes, int n_in,
                              void* d_out, int out_size) {
    const float* x  = nullptr;
    const float* tf = nullptr;
    const float* W  = nullptr;
    for (int i = 0; i < n_in; i++) {
        if (in_sizes[i] == NB * CIN * HH * WW)        x  = (const float*)d_in[i];
        else if (in_sizes[i] == NB * NT * NK)         tf = (const float*)d_in[i];
        else if (in_sizes[i] == NK * COUT * CIN * 25) W  = (const float*)d_in[i];
    }
    float* out = (float*)d_out;

    static cudaStream_t s2 = make_stream();
    static cudaEvent_t  eA = make_event();
    static cudaEvent_t  eB = make_event();
    static cudaEvent_t  eC = make_event();

    // main stream: lp for b0-7, then lp for b8-15 (overlaps with convA on s2)
    lp_kernel<<<800, 256>>>(W, tf, 0);
    cudaEventRecord(eA, 0);
    cudaStreamWaitEvent(s2, eA, 0);
    conv_kernel<<<dim3(16, 8), 512, 0, s2>>>(x, out, 0);

    lp_kernel<<<800, 256>>>(W, tf, 8);
    cudaEventRecord(eB, 0);
    cudaStreamWaitEvent(s2, eB, 0);
    conv_kernel<<<dim3(16, 8), 512, 0, s2>>>(x, out, 8);

    cudaEventRecord(eC, s2);
    cudaStreamWaitEvent(0, eC, 0);
}

// round 9
// speedup vs baseline: 1.0060x; 1.0060x over previous
#include <cuda_runtime.h>
#include <cstdint>

typedef unsigned long long ull;

// Problem constants
#define NB   16
#define NT   8
#define NK   64
#define CIN  128
#define COUT 128
#define HH   64
#define WW   64

// g_lp: fp16x2 weights in m16n8k16 A-fragment order:
// [b][ij 25][kc 8][mt 8][lane 32][q 4]   (b stride 204800, ij stride 8192, kc stride 1024)
// element (oc, cin): kc=cin>>4, cp=(cin>>1)&7, lo=cin&1 (lo->low half of fp16x2);
//                    kb=cp&3, qk=cp>>2; rl=oc&15, mt=oc>>4, rg=rl&7, qr=rl>>3;
//                    lane=rg*4+kb, q=qk*2+qr
__device__ uint32_t g_lp[NB * 204800];

// ---------------- helpers ----------------
__device__ __forceinline__ ull bcast2(float x) {
    ull r; asm("mov.b64 %0, {%1, %1};" : "=l"(r) : "f"(x)); return r;
}
__device__ __forceinline__ ull pack2(float lo, float hi) {
    ull r; asm("mov.b64 %0, {%1, %2};" : "=l"(r) : "f"(lo), "f"(hi)); return r;
}
__device__ __forceinline__ void unpack2(ull v, float& lo, float& hi) {
    asm("mov.b64 {%0, %1}, %2;" : "=f"(lo), "=f"(hi) : "l"(v));
}
__device__ __forceinline__ void ffma2(ull& d, ull a, ull b) {
    asm("fma.rn.f32x2 %0, %1, %2, %3;" : "=l"(d) : "l"(a), "l"(b), "l"(d));
}
// pack two f32 into fp16x2: lo -> low 16 bits, hi -> high 16 bits
__device__ __forceinline__ uint32_t pack_h2(float lo, float hi) {
    uint32_t v; asm("cvt.rn.f16x2.f32 %0, %1, %2;" : "=r"(v) : "f"(hi), "f"(lo)); return v;
}
// m16n8k16 fp16 MMA: D(16x8,f32) += A(16x16 f16, row) * B(16x8 f16, col)
__device__ __forceinline__ void mma_f16(float* d, const uint4& a, uint32_t b0, uint32_t b1) {
    asm volatile(
        "mma.sync.aligned.m16n8k16.row.col.f32.f16.f16.f32 "
        "{%0,%1,%2,%3}, {%4,%5,%6,%7}, {%8,%9}, {%0,%1,%2,%3};\n"
        : "+f"(d[0]), "+f"(d[1]), "+f"(d[2]), "+f"(d[3])
        : "r"(a.x), "r"(a.y), "r"(a.z), "r"(a.w), "r"(b0), "r"(b1));
}

// ---------------- lp kernel: inline coeff + fragment-ordered fp16x2 params, all 16 b ----------------
__global__ void lp_kernel(const float* __restrict__ W, const float* __restrict__ tf) {
    __shared__ ull sc[NK * 8];    // [k][pair p of 8], pair p -> b = 2p / 2p+1
    int tid = threadIdx.x;        // 256

    // inline coeff: 512 entries, 2 per thread
#pragma unroll
    for (int e = tid; e < NK * 8; e += 256) {
        int k = e >> 3;
        int p = e & 7;
        float s0 = 0.f, s1 = 0.f;
#pragma unroll
        for (int tt = 0; tt < NT; tt++) {
            s0 += tf[((2 * p) * NT + tt) * NK + k];
            s1 += tf[((2 * p + 1) * NT + tt) * NK + k];
        }
        sc[k * 8 + p] = pack2(s0 * 0.125f, s1 * 0.125f);
    }
    __syncthreads();

    int idx = blockIdx.x * 256 + tid;   // < 204800 (grid 800)
    int o   = idx / 1600;
    int rem = idx - o * 1600;
    int cp  = rem / 25;
    int ij  = rem - cp * 25;

    const float* W0 = W + o * 3200 + (2 * cp) * 25 + ij;        // even cin
    const float* W1 = W0 + 25;                                  // odd cin

    ull a0[8], a1[8];
#pragma unroll
    for (int p = 0; p < 8; p++) { a0[p] = 0ULL; a1[p] = 0ULL; }

#pragma unroll 4
    for (int k = 0; k < NK; k++) {
        ull w0 = bcast2(W0[k * 409600]);
        ull w1 = bcast2(W1[k * 409600]);
#pragma unroll
        for (int p = 0; p < 8; p++) {
            ffma2(a0[p], w0, sc[k * 8 + p]);
            ffma2(a1[p], w1, sc[k * 8 + p]);
        }
    }

    // fragment-order output index
    int kc = cp >> 3, cpl = cp & 7;
    int kb = cpl & 3, qk = cpl >> 2;
    int rl = o & 15, mt = o >> 4;
    int rg = rl & 7, qr = rl >> 3;
    int outoff = ij * 8192 + kc * 1024 + mt * 128 + (rg * 4 + kb) * 4 + (qk * 2 + qr);

#pragma unroll
    for (int p = 0; p < 8; p++) {
        float e0, e1, d0, d1;
        unpack2(a0[p], e0, e1);   // even cin, b = 2p / 2p+1
        unpack2(a1[p], d0, d1);   // odd  cin
        g_lp[(2 * p) * 204800 + outoff]     = pack_h2(e0, d0);
        g_lp[(2 * p + 1) * 204800 + outoff] = pack_h2(e1, d1);
    }
}

// ---------------- conv kernel: implicit-GEMM via mma.sync fp16 k16, 2 CTAs/SM ----------------
// CTA: 256 threads, 8 warps (mrow2 = wid&1, ro = wid>>1). Covers 64 oc x 4 rows x 64 w.
// grid: (16 row-tiles, 2 oc-blocks, 16 b) = 512 CTAs.
// x tile in smem: 8 cin-pairs x 8 rows x 72 w fp16x2 (stride 584 -> conflict-free B frags).
#define XSTRIDE 584

__global__ void __launch_bounds__(256, 2)
conv_kernel(const float* __restrict__ x, float* __restrict__ out) {
    __shared__ uint32_t sx[8 * XSTRIDE];   // 18688 B

    int tid  = threadIdx.x;
    int lane = tid & 31, wid = tid >> 5;
    int mrow2 = wid & 1, ro = wid >> 1;    // mrow2: 32-oc half of this CTA's 64 oc; ro: row 0..3
    int ocb  = blockIdx.y;
    int b    = blockIdx.z;

    const float*    xb  = x + b * CIN * (HH * WW);
    const uint32_t* lpb = g_lp + b * 204800;
    // mt base = ocb*4 + mrow2*2  (mt stride = 128 words)
    const uint32_t* abase = lpb + (ocb * 4 + mrow2 * 2) * 128 + lane * 4;

    int g  = lane >> 2;
    int m4 = lane & 3;

    int r0 = blockIdx.x * 4;

    float d[2][8][4];
#pragma unroll
    for (int mt = 0; mt < 2; mt++)
#pragma unroll
        for (int nt = 0; nt < 8; nt++)
#pragma unroll
            for (int q = 0; q < 4; q++) d[mt][nt][q] = 0.f;

    // prefetch A fragments for it = 0 (ij=0, kc=0); mt stride = 128 words = 32 uint4
    uint4 An0, An1;
    {
        const uint4* p = (const uint4*)abase;
        An0 = p[0]; An1 = p[32];
    }

    for (int it = 0; it < 200; it++) {
        int c0i = it / 25, ij = it - c0i * 25;

        if (ij == 0) {
            __syncthreads();
            int c0 = c0i * 16;
            for (int q = tid; q < 8 * 576; q += 256) {
                int pr = q / 576, r = q - pr * 576;
                int ur = r / 72, uc = r - ur * 72;
                int gh = r0 + ur - 2, gw = uc - 2;
                float v0 = 0.f, v1 = 0.f;
                if (gh >= 0 && gh < HH && gw >= 0 && gw < WW) {
                    const float* px = xb + ((c0 + 2 * pr) << 12) + (gh << 6) + gw;
                    v0 = px[0];
                    v1 = px[1 << 12];
                }
                sx[pr * XSTRIDE + ur * 72 + uc] = pack_h2(v0, v1);
            }
            __syncthreads();
        }

        uint4 A0 = An0, A1 = An1;
        if (it + 1 < 200) {
            int itn = it + 1;
            int c0n = itn / 25, ijn = itn - c0n * 25;
            const uint4* p = (const uint4*)(abase + ijn * 8192 + c0n * 1024);
            An0 = p[0]; An1 = p[32];
        }

        int i = ij / 5, j = ij - i * 5;
        int boff = m4 * XSTRIDE + (ro + i) * 72 + j + g;
#pragma unroll
        for (int nt = 0; nt < 8; nt++) {
            uint32_t b0 = sx[boff + nt * 8];
            uint32_t b1 = sx[boff + nt * 8 + 4 * XSTRIDE];
            mma_f16(d[0][nt], A0, b0, b1);
            mma_f16(d[1][nt], A1, b0, b1);
        }
    }

    // epilogue: D(row=g/g+8, col=2*m4/2*m4+1) per (mt, nt)
    int h = r0 + ro;
#pragma unroll
    for (int mt = 0; mt < 2; mt++) {
#pragma unroll
        for (int qr = 0; qr < 2; qr++) {
            int oc = ocb * 64 + mrow2 * 32 + mt * 16 + g + qr * 8;
            float* op = out + ((b * COUT + oc) * HH + h) * WW;
#pragma unroll
            for (int nt = 0; nt < 8; nt++) {
                float2 v;
                v.x = d[mt][nt][qr * 2];
                v.y = d[mt][nt][qr * 2 + 1];
                *(float2*)(op + nt * 8 + 2 * m4) = v;
            }
        }
    }
}

extern "C" void kernel_launch(void* const* d_in, const int* in_sizes, int n_in,
                              void* d_out, int out_size) {
    const float* x  = nullptr;
    const float* tf = nullptr;
    const float* W  = nullptr;
    for (int i = 0; i < n_in; i++) {
        if (in_sizes[i] == NB * CIN * HH * WW)        x  = (const float*)d_in[i];
        else if (in_sizes[i] == NB * NT * NK)         tf = (const float*)d_in[i];
        else if (in_sizes[i] == NK * COUT * CIN * 25) W  = (const float*)d_in[i];
    }
    float* out = (float*)d_out;

    lp_kernel<<<800, 256>>>(W, tf);
    conv_kernel<<<dim3(16, 2, NB), 256>>>(x, out);
}

// round 10
// speedup vs baseline: 1.3657x; 1.3576x over previous
#include <cuda_runtime.h>
#include <cstdint>

typedef unsigned long long ull;

// Problem constants
#define NB   16
#define NT   8
#define NK   64
#define CIN  128
#define COUT 128
#define HH   64
#define WW   64

// g_lp: fp16x2 weights in m16n8k16 A-fragment order:
// [b][ij 25][kc 8][mt 8][lane 32][q 4]   (b stride 204800, ij stride 8192, kc stride 1024)
// element (oc, cin): kc=cin>>4, cp=(cin>>1)&7, lo=cin&1 (lo->low half of fp16x2);
//                    kb=cp&3, qk=cp>>2; rl=oc&15, mt=oc>>4, rg=rl&7, qr=rl>>3;
//                    lane=rg*4+kb, q=qk*2+qr
__device__ uint32_t g_lp[NB * 204800];

// ---------------- helpers ----------------
__device__ __forceinline__ ull bcast2(float x) {
    ull r; asm("mov.b64 %0, {%1, %1};" : "=l"(r) : "f"(x)); return r;
}
__device__ __forceinline__ ull pack2(float lo, float hi) {
    ull r; asm("mov.b64 %0, {%1, %2};" : "=l"(r) : "f"(lo), "f"(hi)); return r;
}
__device__ __forceinline__ void unpack2(ull v, float& lo, float& hi) {
    asm("mov.b64 {%0, %1}, %2;" : "=f"(lo), "=f"(hi) : "l"(v));
}
__device__ __forceinline__ void ffma2(ull& d, ull a, ull b) {
    asm("fma.rn.f32x2 %0, %1, %2, %3;" : "=l"(d) : "l"(a), "l"(b), "l"(d));
}
// pack two f32 into fp16x2: lo -> low 16 bits, hi -> high 16 bits
__device__ __forceinline__ uint32_t pack_h2(float lo, float hi) {
    uint32_t v; asm("cvt.rn.f16x2.f32 %0, %1, %2;" : "=r"(v) : "f"(hi), "f"(lo)); return v;
}
// m16n8k16 fp16 MMA: D(16x8,f32) += A(16x16 f16, row) * B(16x8 f16, col)
__device__ __forceinline__ void mma_f16(float* d, const uint4& a, uint32_t b0, uint32_t b1) {
    asm volatile(
        "mma.sync.aligned.m16n8k16.row.col.f32.f16.f16.f32 "
        "{%0,%1,%2,%3}, {%4,%5,%6,%7}, {%8,%9}, {%0,%1,%2,%3};\n"
        : "+f"(d[0]), "+f"(d[1]), "+f"(d[2]), "+f"(d[3])
        : "r"(a.x), "r"(a.y), "r"(a.z), "r"(a.w), "r"(b0), "r"(b1));
}

// ---------------- lp kernel: inline coeff + fragment-ordered fp16x2 params, all 16 b ----------------
__global__ void lp_kernel(const float* __restrict__ W, const float* __restrict__ tf) {
    __shared__ ull sc[NK * 8];    // [k][pair p of 8], pair p -> b = 2p / 2p+1
    int tid = threadIdx.x;        // 256

    // inline coeff: 512 entries, 2 per thread
#pragma unroll
    for (int e = tid; e < NK * 8; e += 256) {
        int k = e >> 3;
        int p = e & 7;
        float s0 = 0.f, s1 = 0.f;
#pragma unroll
        for (int tt = 0; tt < NT; tt++) {
            s0 += tf[((2 * p) * NT + tt) * NK + k];
            s1 += tf[((2 * p + 1) * NT + tt) * NK + k];
        }
        sc[k * 8 + p] = pack2(s0 * 0.125f, s1 * 0.125f);
    }
    __syncthreads();

    int idx = blockIdx.x * 256 + tid;   // < 204800 (grid 800)
    int o   = idx / 1600;
    int rem = idx - o * 1600;
    int cp  = rem / 25;
    int ij  = rem - cp * 25;

    const float* W0 = W + o * 3200 + (2 * cp) * 25 + ij;        // even cin
    const float* W1 = W0 + 25;                                  // odd cin

    ull a0[8], a1[8];
#pragma unroll
    for (int p = 0; p < 8; p++) { a0[p] = 0ULL; a1[p] = 0ULL; }

#pragma unroll 4
    for (int k = 0; k < NK; k++) {
        ull w0 = bcast2(W0[k * 409600]);
        ull w1 = bcast2(W1[k * 409600]);
#pragma unroll
        for (int p = 0; p < 8; p++) {
            ffma2(a0[p], w0, sc[k * 8 + p]);
            ffma2(a1[p], w1, sc[k * 8 + p]);
        }
    }

    // fragment-order output index
    int kc = cp >> 3, cpl = cp & 7;
    int kb = cpl & 3, qk = cpl >> 2;
    int rl = o & 15, mt = o >> 4;
    int rg = rl & 7, qr = rl >> 3;
    int outoff = ij * 8192 + kc * 1024 + mt * 128 + (rg * 4 + kb) * 4 + (qk * 2 + qr);

#pragma unroll
    for (int p = 0; p < 8; p++) {
        float e0, e1, d0, d1;
        unpack2(a0[p], e0, e1);   // even cin, b = 2p / 2p+1
        unpack2(a1[p], d0, d1);   // odd  cin
        g_lp[(2 * p) * 204800 + outoff]     = pack_h2(e0, d0);
        g_lp[(2 * p + 1) * 204800 + outoff] = pack_h2(e1, d1);
    }
}

// ---------------- conv kernel: implicit-GEMM via mma.sync fp16 k16, static addressing ----------------
// CTA: b x 8-row supertile (2 sequential 4-row tiles). 512 threads, 16 warps.
// Warp (mrow = wid&3, ro = wid>>2): 32 oc x 64 w of output row r0+ro.
// x tile in smem: 8 cin-pairs x 8 rows x 72 w fp16x2 (stride 584 -> conflict-free B frags).
#define XSTRIDE 584

__global__ void __launch_bounds__(512, 1)
conv_kernel(const float* __restrict__ x, float* __restrict__ out) {
    __shared__ uint32_t sx[8 * XSTRIDE];   // 18688 B

    int tid  = threadIdx.x;
    int lane = tid & 31, wid = tid >> 5;
    int mrow = wid & 3, ro = wid >> 2;
    int b    = blockIdx.y;

    const float*    xb  = x + b * CIN * (HH * WW);
    const uint32_t* lpb = g_lp + b * 204800;
    const uint32_t* abase = lpb + mrow * 256 + lane * 4;   // mt = 2*mrow

    int g  = lane >> 2;
    int m4 = lane & 3;
    int bbase = m4 * XSTRIDE + ro * 72 + g;

    for (int tile = 0; tile < 2; tile++) {
        int r0 = blockIdx.x * 8 + tile * 4;

        float d[2][8][4];
#pragma unroll
        for (int mt = 0; mt < 2; mt++)
#pragma unroll
            for (int nt = 0; nt < 8; nt++)
#pragma unroll
                for (int q = 0; q < 4; q++) d[mt][nt][q] = 0.f;

        // A prefetch registers (1 ij ahead); mt stride = 128 words
        const uint32_t* ap = abase;                 // current chunk base
        uint4 An0 = *(const uint4*)(ap);
        uint4 An1 = *(const uint4*)(ap + 128);

        for (int c0i = 0; c0i < 8; c0i++) {
            __syncthreads();
            {
                int c0 = c0i * 16;
                for (int q = tid; q < 8 * 576; q += 512) {
                    int pr = q / 576, r = q - pr * 576;
                    int ur = r / 72, uc = r - ur * 72;
                    int gh = r0 + ur - 2, gw = uc - 2;
                    float v0 = 0.f, v1 = 0.f;
                    if (gh >= 0 && gh < HH && gw >= 0 && gw < WW) {
                        const float* px = xb + ((c0 + 2 * pr) << 12) + (gh << 6) + gw;
                        v0 = px[0];
                        v1 = px[1 << 12];
                    }
                    sx[pr * XSTRIDE + ur * 72 + uc] = pack_h2(v0, v1);
                }
            }
            __syncthreads();

            const uint32_t* apn = (c0i < 7) ? (ap + 1024) : ap;   // next chunk (clamped)

#pragma unroll
            for (int ij = 0; ij < 25; ij++) {
                uint4 A0 = An0, A1 = An1;
                // prefetch next ij (static offsets after unroll)
                const uint32_t* pn = (ij < 24) ? (ap + (ij + 1) * 8192) : apn;
                An0 = *(const uint4*)(pn);
                An1 = *(const uint4*)(pn + 128);

                const int i = ij / 5;          // compile-time after unroll
                const int j = ij - i * 5;
                const int boff = bbase + i * 72 + j;
#pragma unroll
                for (int nt = 0; nt < 8; nt++) {
                    uint32_t b0 = sx[boff + nt * 8];
                    uint32_t b1 = sx[boff + nt * 8 + 4 * XSTRIDE];
                    mma_f16(d[0][nt], A0, b0, b1);
                    mma_f16(d[1][nt], A1, b0, b1);
                }
            }
            ap += 1024;
        }

        // epilogue: D(row=g/g+8, col=2*m4/2*m4+1) per (mt, nt)
        int h = r0 + ro;
#pragma unroll
        for (int mt = 0; mt < 2; mt++) {
#pragma unroll
            for (int qr = 0; qr < 2; qr++) {
                int oc = mrow * 32 + mt * 16 + g + qr * 8;
                float* op = out + ((b * COUT + oc) * HH + h) * WW;
#pragma unroll
                for (int nt = 0; nt < 8; nt++) {
                    float2 v;
                    v.x = d[mt][nt][qr * 2];
                    v.y = d[mt][nt][qr * 2 + 1];
                    *(float2*)(op + nt * 8 + 2 * m4) = v;
                }
            }
        }
    }
}

extern "C" void kernel_launch(void* const* d_in, const int* in_sizes, int n_in,
                              void* d_out, int out_size) {
    const float* x  = nullptr;
    const float* tf = nullptr;
    const float* W  = nullptr;
    for (int i = 0; i < n_in; i++) {
        if (in_sizes[i] == NB * CIN * HH * WW)        x  = (const float*)d_in[i];
        else if (in_sizes[i] == NB * NT * NK)         tf = (const float*)d_in[i];
        else if (in_sizes[i] == NK * COUT * CIN * 25) W  = (const float*)d_in[i];
    }
    float* out = (float*)d_out;

    lp_kernel<<<800, 256>>>(W, tf);
    conv_kernel<<<dim3(8, NB), 512>>>(x, out);
}